// round 2
// baseline (speedup 1.0000x reference)
#include <cuda_runtime.h>
#include <cstdint>

// Problem constants
#define BATCH 2
#define SEQ   2048
#define HID   1024
#define HEADS 16
#define HDIM  64
#define QKVW  (3*HID)      // 3072
#define MROWS (BATCH*SEQ)  // 4096

// Scratch (device globals — no allocation allowed)
__device__ float g_qkv[(size_t)MROWS * QKVW];   // [B,S,3,H,D]
__device__ float g_att[(size_t)MROWS * HID];    // [B,S,H,D]

// ---------------------------------------------------------------------------
// SGEMM with fused bias:  C[M,N] = A[M,K] @ B[K,N] + bias[N]
// BM=128 BN=128 BK=16, 256 threads, 8x8 per thread. M,N %128==0, K%16==0.
// ---------------------------------------------------------------------------
#define BM 128
#define BN 128
#define BK 16

__global__ __launch_bounds__(256) void sgemm_bias(
    const float* __restrict__ A, const float* __restrict__ B,
    const float* __restrict__ bias, float* __restrict__ C,
    int M, int N, int K)
{
    __shared__ float As[BK][BM];   // transposed A tile
    __shared__ float Bs[BK][BN];

    const int tid = threadIdx.x;
    const int m0 = blockIdx.y * BM;
    const int n0 = blockIdx.x * BN;

    const int rm = (tid >> 4) * 8;   // 0..120
    const int rn = (tid & 15) * 8;   // 0..120

    float acc[8][8];
#pragma unroll
    for (int i = 0; i < 8; i++)
#pragma unroll
        for (int j = 0; j < 8; j++) acc[i][j] = 0.0f;

    for (int k0 = 0; k0 < K; k0 += BK) {
        // Load A tile: 128 rows x 16 cols = 512 float4
#pragma unroll
        for (int i = 0; i < 2; i++) {
            int lin = tid + i * 256;
            int row = lin >> 2;
            int c4  = (lin & 3) * 4;
            float4 v = *(const float4*)(A + (size_t)(m0 + row) * K + k0 + c4);
            As[c4 + 0][row] = v.x;
            As[c4 + 1][row] = v.y;
            As[c4 + 2][row] = v.z;
            As[c4 + 3][row] = v.w;
        }
        // Load B tile: 16 rows x 128 cols = 512 float4
#pragma unroll
        for (int i = 0; i < 2; i++) {
            int lin = tid + i * 256;
            int row = lin >> 5;
            int c4  = (lin & 31) * 4;
            *(float4*)&Bs[row][c4] =
                *(const float4*)(B + (size_t)(k0 + row) * N + n0 + c4);
        }
        __syncthreads();

#pragma unroll
        for (int k = 0; k < BK; k++) {
            float a[8], bb[8];
#pragma unroll
            for (int i = 0; i < 8; i++) a[i] = As[k][rm + i];
#pragma unroll
            for (int j = 0; j < 8; j++) bb[j] = Bs[k][rn + j];
#pragma unroll
            for (int i = 0; i < 8; i++)
#pragma unroll
                for (int j = 0; j < 8; j++)
                    acc[i][j] += a[i] * bb[j];
        }
        __syncthreads();
    }

    float bv[8];
#pragma unroll
    for (int j = 0; j < 8; j++) bv[j] = bias[n0 + rn + j];

#pragma unroll
    for (int i = 0; i < 8; i++) {
        float* crow = C + (size_t)(m0 + rm + i) * N + n0 + rn;
#pragma unroll
        for (int j0 = 0; j0 < 8; j0 += 4) {
            float4 v;
            v.x = acc[i][j0 + 0] + bv[j0 + 0];
            v.y = acc[i][j0 + 1] + bv[j0 + 1];
            v.z = acc[i][j0 + 2] + bv[j0 + 2];
            v.w = acc[i][j0 + 3] + bv[j0 + 3];
            *(float4*)(crow + j0) = v;
        }
    }
}

// ---------------------------------------------------------------------------
// RoPE in-place on q,k slices of g_qkv. One thread per (pair).
// qkv layout: [B,S,3,H,D]; cache: [256][32][2] (cos,sin)
// ---------------------------------------------------------------------------
__global__ void rope_kernel(float* __restrict__ qkv, const float* __restrict__ cache)
{
    int i = blockIdx.x * blockDim.x + threadIdx.x;
    const int total = BATCH * SEQ * 2 * HEADS * (HDIM / 2); // 4194304
    if (i >= total) return;
    int d2   = i & 31;
    int h    = (i >> 5) & 15;
    int kind = (i >> 9) & 1;        // 0=q, 1=k
    int s    = (i >> 10) & (SEQ - 1);
    int b    = i >> 21;

    size_t base = ((size_t)(b * SEQ + s)) * QKVW + kind * HID + h * HDIM + d2 * 2;
    float2 x  = *(float2*)(qkv + base);
    int pos = s & 255;
    float2 cs = *(const float2*)(cache + (pos * 32 + d2) * 2);
    float y0 = x.x * cs.x - x.y * cs.y;
    float y1 = x.y * cs.x + x.x * cs.y;
    *(float2*)(qkv + base) = make_float2(y0, y1);
}

// ---------------------------------------------------------------------------
// Banded attention. Block = (q-tile of 64, head, batch). 256 threads.
// Key window for q-tile [q0, q0+63]:  [q0-128, q0+191]  (320 keys, 5 tiles).
// Scores strip [64][320] lives in SMEM (exact softmax, no online pass).
// ---------------------------------------------------------------------------
#define QT   64
#define KTIL 5
#define KW   (KTIL*64)   // 320
#define QS   65          // padded row stride for q/k/v tiles
#define SCW  321         // padded row stride for score strip

__global__ __launch_bounds__(256) void attn_kernel(
    const float* __restrict__ qkv, float* __restrict__ att)
{
    extern __shared__ float sm[];
    float* q_s  = sm;                      // [64][QS]
    float* kv_s = sm + QT * QS;            // [64][QS]
    float* sc   = sm + 2 * QT * QS;        // [64][SCW]
    float* red  = sc + QT * SCW;           // [4][64]

    const int tid = threadIdx.x;
    const int q0 = blockIdx.x * QT;
    const int h  = blockIdx.y;
    const int b  = blockIdx.z;
    const int kb = q0 - 128;

    const float* qbase = qkv + ((size_t)(b * SEQ + q0)) * QKVW + h * HDIM;

    // Load q tile (64 rows x 64 floats)
#pragma unroll
    for (int i = 0; i < 4; i++) {
        int lin = tid + i * 256;
        int r  = lin >> 4;
        int c4 = (lin & 15) * 4;
        float4 v = *(const float4*)(qbase + (size_t)r * QKVW + c4);
        q_s[r * QS + c4 + 0] = v.x;
        q_s[r * QS + c4 + 1] = v.y;
        q_s[r * QS + c4 + 2] = v.z;
        q_s[r * QS + c4 + 3] = v.w;
    }

    const int tr = tid >> 4, tc = tid & 15;
    const int rm = tr * 4, cn = tc * 4;
    const float scale = 0.125f;   // 1/sqrt(64)

    // ---- Phase 1: scores ----
    for (int t = 0; t < KTIL; t++) {
        __syncthreads();
        // load K tile (zeros if key OOB)
#pragma unroll
        for (int i = 0; i < 4; i++) {
            int lin = tid + i * 256;
            int r  = lin >> 4;
            int c4 = (lin & 15) * 4;
            int kj = kb + t * 64 + r;
            float4 v = make_float4(0.f, 0.f, 0.f, 0.f);
            if (kj >= 0 && kj < SEQ)
                v = *(const float4*)(qkv + ((size_t)(b * SEQ + kj)) * QKVW + HID + h * HDIM + c4);
            kv_s[r * QS + c4 + 0] = v.x;
            kv_s[r * QS + c4 + 1] = v.y;
            kv_s[r * QS + c4 + 2] = v.z;
            kv_s[r * QS + c4 + 3] = v.w;
        }
        __syncthreads();

        float acc[4][4];
#pragma unroll
        for (int i = 0; i < 4; i++)
#pragma unroll
            for (int j = 0; j < 4; j++) acc[i][j] = 0.0f;

#pragma unroll 8
        for (int d = 0; d < HDIM; d++) {
            float a[4], bb[4];
#pragma unroll
            for (int i = 0; i < 4; i++) a[i] = q_s[(rm + i) * QS + d];
#pragma unroll
            for (int j = 0; j < 4; j++) bb[j] = kv_s[(cn + j) * QS + d];
#pragma unroll
            for (int i = 0; i < 4; i++)
#pragma unroll
                for (int j = 0; j < 4; j++)
                    acc[i][j] += a[i] * bb[j];
        }

#pragma unroll
        for (int i = 0; i < 4; i++) {
            int qi = q0 + rm + i;
#pragma unroll
            for (int j = 0; j < 4; j++) {
                int kj = kb + t * 64 + cn + j;
                int rel = qi - kj;
                bool valid = (kj >= 0) && (kj < SEQ) && (rel <= 128) && (rel >= -128);
                sc[(rm + i) * SCW + t * 64 + cn + j] = valid ? acc[i][j] * scale : -1e30f;
            }
        }
    }
    __syncthreads();

    // ---- Phase 2: softmax over 320 cols, 4 threads per row ----
    {
        const int part = tid >> 6;      // 0..3
        const int row  = tid & 63;
        const int c0 = part * 80;
        float mx = -1e30f;
        for (int c = c0; c < c0 + 80; c++) mx = fmaxf(mx, sc[row * SCW + c]);
        red[part * 64 + row] = mx;
        __syncthreads();
        float m = fmaxf(fmaxf(red[row], red[64 + row]),
                        fmaxf(red[128 + row], red[192 + row]));
        __syncthreads();   // all reads of red done before overwrite
        float sumv = 0.0f;
        for (int c = c0; c < c0 + 80; c++) {
            float e = __expf(sc[row * SCW + c] - m);
            sc[row * SCW + c] = e;
            sumv += e;
        }
        red[part * 64 + row] = sumv;
    }
    __syncthreads();

    // ---- Phase 3: PV  out[64][64] = sc[64][320] @ V[320][64] ----
    float acc2[4][4];
#pragma unroll
    for (int i = 0; i < 4; i++)
#pragma unroll
        for (int j = 0; j < 4; j++) acc2[i][j] = 0.0f;

    const int dn = tc * 4;
    for (int t = 0; t < KTIL; t++) {
        __syncthreads();
#pragma unroll
        for (int i = 0; i < 4; i++) {
            int lin = tid + i * 256;
            int r  = lin >> 4;
            int c4 = (lin & 15) * 4;
            int kj = kb + t * 64 + r;
            float4 v = make_float4(0.f, 0.f, 0.f, 0.f);
            if (kj >= 0 && kj < SEQ)
                v = *(const float4*)(qkv + ((size_t)(b * SEQ + kj)) * QKVW + 2 * HID + h * HDIM + c4);
            kv_s[r * QS + c4 + 0] = v.x;
            kv_s[r * QS + c4 + 1] = v.y;
            kv_s[r * QS + c4 + 2] = v.z;
            kv_s[r * QS + c4 + 3] = v.w;
        }
        __syncthreads();

#pragma unroll 8
        for (int c = 0; c < 64; c++) {
            float a[4], bb[4];
#pragma unroll
            for (int i = 0; i < 4; i++) a[i] = sc[(rm + i) * SCW + t * 64 + c];
#pragma unroll
            for (int j = 0; j < 4; j++) bb[j] = kv_s[c * QS + dn + j];
#pragma unroll
            for (int i = 0; i < 4; i++)
#pragma unroll
                for (int j = 0; j < 4; j++)
                    acc2[i][j] += a[i] * bb[j];
        }
    }

    // epilogue: divide by row sums and store to att [B,S,H,D]
#pragma unroll
    for (int i = 0; i < 4; i++) {
        int r = rm + i;
        float rs = red[r] + red[64 + r] + red[128 + r] + red[192 + r];
        float inv = 1.0f / rs;
        int qi = q0 + r;
        float4 v;
        v.x = acc2[i][0] * inv;
        v.y = acc2[i][1] * inv;
        v.z = acc2[i][2] * inv;
        v.w = acc2[i][3] * inv;
        *(float4*)(att + ((size_t)((b * SEQ + qi) * HEADS + h)) * HDIM + dn) = v;
    }
}

// ---------------------------------------------------------------------------
// Launch
// ---------------------------------------------------------------------------
extern "C" void kernel_launch(void* const* d_in, const int* in_sizes, int n_in,
                              void* d_out, int out_size)
{
    const float* hs   = (const float*)d_in[0];
    const float* wqkv = (const float*)d_in[1];
    const float* bqkv = (const float*)d_in[2];
    const float* wo   = (const float*)d_in[3];
    const float* bo   = (const float*)d_in[4];
    const float* rope = (const float*)d_in[5];
    float* out = (float*)d_out;

    float* qkv = nullptr;
    float* att = nullptr;
    cudaGetSymbolAddress((void**)&qkv, g_qkv);
    cudaGetSymbolAddress((void**)&att, g_att);

    // 1) QKV projection
    sgemm_bias<<<dim3(QKVW / BN, MROWS / BM), 256>>>(hs, wqkv, bqkv, qkv,
                                                     MROWS, QKVW, HID);
    // 2) RoPE on q,k
    {
        const int total = BATCH * SEQ * 2 * HEADS * (HDIM / 2);
        rope_kernel<<<(total + 255) / 256, 256>>>(qkv, rope);
    }
    // 3) Banded attention
    {
        const int smem = (2 * QT * QS + QT * SCW + 4 * 64) * (int)sizeof(float);
        cudaFuncSetAttribute(attn_kernel,
                             cudaFuncAttributeMaxDynamicSharedMemorySize, smem);
        attn_kernel<<<dim3(SEQ / QT, HEADS, BATCH), 256, smem>>>(qkv, att);
    }
    // 4) Output projection
    sgemm_bias<<<dim3(HID / BN, MROWS / BM), 256>>>(att, wo, bo, out,
                                                    MROWS, HID, HID);
}

// round 6
// speedup vs baseline: 1.9930x; 1.9930x over previous
#include <cuda_runtime.h>
#include <cuda_bf16.h>
#include <cstdint>

// Problem constants
#define BATCH 2
#define SEQ   2048
#define HID   1024
#define HEADS 16
#define HDIM  64
#define QKVW  (3*HID)      // 3072
#define MROWS (BATCH*SEQ)  // 4096
#define KDIM  1024

// Scratch (device globals — no allocation allowed)
__device__ float g_qkv[(size_t)MROWS * QKVW];   // [B,S,3,H,D]
__device__ float g_att[(size_t)MROWS * HID];    // [B,S,H,D]

// ---------------------------------------------------------------------------
// tf32 helpers
// ---------------------------------------------------------------------------
__device__ __forceinline__ float tf32r(float x) {
    uint32_t u;
    asm("cvt.rna.tf32.f32 %0, %1;" : "=r"(u) : "f"(x));
    return __uint_as_float(u);
}

__device__ __forceinline__ void mma_tf32(float* d, const uint32_t* a, const uint32_t* b) {
    asm volatile(
        "mma.sync.aligned.m16n8k8.row.col.f32.tf32.tf32.f32 "
        "{%0,%1,%2,%3}, {%4,%5,%6,%7}, {%8,%9}, {%0,%1,%2,%3};\n"
        : "+f"(d[0]), "+f"(d[1]), "+f"(d[2]), "+f"(d[3])
        : "r"(a[0]), "r"(a[1]), "r"(a[2]), "r"(a[3]),
          "r"(b[0]), "r"(b[1]));
}

// ---------------------------------------------------------------------------
// tf32 mma GEMM:  C[M,N] = A[M,1024] @ B[1024,N] + bias[N]
// CTA tile 128x128, K-chunk 32, 256 threads (8 warps, 4x2 grid of 32x64).
// Fragment-permuted SMEM: each thread's mma fragment = one vector LDS.
// ---------------------------------------------------------------------------
__global__ __launch_bounds__(256) void gemm_tf32(
    const float* __restrict__ A, const float* __restrict__ B,
    const float* __restrict__ bias, float* __restrict__ C, int N)
{
    __shared__ float As[4096];   // 128 rows x 32 k, fragment-permuted
    __shared__ float Bs[4096];   // 32 k x 128 cols, fragment-permuted

    const int tid  = threadIdx.x;
    const int lane = tid & 31;
    const int wid  = tid >> 5;
    const int wm   = wid >> 1;          // 0..3  (rows)
    const int wn   = wid & 1;           // 0..1  (cols)
    const int m0 = blockIdx.y * 128, n0 = blockIdx.x * 128;

    float acc[2][8][4];
#pragma unroll
    for (int i = 0; i < 2; i++)
#pragma unroll
        for (int j = 0; j < 8; j++)
#pragma unroll
            for (int c = 0; c < 4; c++) acc[i][j][c] = 0.0f;

    float4 pa[4], pb[4];

    // ---- staging helpers (macros keep everything in registers) ----
#define LDG_CHUNK(k0)                                                          \
    {                                                                          \
        _Pragma("unroll")                                                      \
        for (int i = 0; i < 4; i++) {                                          \
            int idx = tid + i * 256;                                           \
            int row = idx >> 3, c4 = (idx & 7) << 2;                           \
            pa[i] = *(const float4*)(A + (size_t)(m0 + row) * KDIM + (k0) + c4);\
            int kk = idx >> 5, n4 = (idx & 31) << 2;                           \
            pb[i] = *(const float4*)(B + (size_t)((k0) + kk) * N + n0 + n4);   \
        }                                                                      \
    }

#define STS_CHUNK()                                                            \
    {                                                                          \
        _Pragma("unroll")                                                      \
        for (int i = 0; i < 4; i++) {                                          \
            int idx = tid + i * 256;                                           \
            /* A element (row, k) -> fragment slot */                          \
            {                                                                  \
                int row = idx >> 3, c4 = (idx & 7) << 2;                       \
                int tm = row >> 4, r = row & 15;                               \
                float v[4] = {pa[i].x, pa[i].y, pa[i].z, pa[i].w};             \
                _Pragma("unroll")                                              \
                for (int j = 0; j < 4; j++) {                                  \
                    int k  = c4 + j;                                           \
                    int tk = k >> 3;                                           \
                    int ln = ((r & 7) << 2) | (k & 3);                         \
                    int rg = (((k >> 2) & 1) << 1) | (r >> 3);                 \
                    As[(((tm << 2) | tk) << 7) + ((ln ^ tk) << 2) + rg] = tf32r(v[j]); \
                }                                                              \
            }                                                                  \
            /* B element (k, n) -> fragment slot */                            \
            {                                                                  \
                int kk = idx >> 5, n4 = (idx & 31) << 2;                       \
                int tk = kk >> 3;                                              \
                int rg = (kk >> 2) & 1;                                        \
                float v[4] = {pb[i].x, pb[i].y, pb[i].z, pb[i].w};             \
                _Pragma("unroll")                                              \
                for (int j = 0; j < 4; j++) {                                  \
                    int n  = n4 + j;                                           \
                    int tn = n >> 3;                                           \
                    int ln = ((n & 7) << 2) | (kk & 3);                        \
                    Bs[((tk * 16 + tn) << 6) + ((ln ^ (tn & 7)) << 1) + rg] = tf32r(v[j]); \
                }                                                              \
            }                                                                  \
        }                                                                      \
    }

    LDG_CHUNK(0);
    STS_CHUNK();
    __syncthreads();

    for (int ck = 0; ck < KDIM / 32; ck++) {
        if (ck < KDIM / 32 - 1) LDG_CHUNK((ck + 1) * 32);

        // compute on current smem chunk
#pragma unroll
        for (int kt = 0; kt < 4; kt++) {
            uint4 a[2];
            uint2 b[8];
#pragma unroll
            for (int mt = 0; mt < 2; mt++) {
                int tile = ((wm * 2 + mt) << 2) | kt;
                a[mt] = ((const uint4*)As)[(tile << 5) + (lane ^ kt)];
            }
#pragma unroll
            for (int nt = 0; nt < 8; nt++) {
                int tn = wn * 8 + nt;
                b[nt] = ((const uint2*)Bs)[((kt * 16 + tn) << 5) + (lane ^ (tn & 7))];
            }
#pragma unroll
            for (int mt = 0; mt < 2; mt++)
#pragma unroll
                for (int nt = 0; nt < 8; nt++)
                    mma_tf32(acc[mt][nt], (const uint32_t*)&a[mt], (const uint32_t*)&b[nt]);
        }
        __syncthreads();
        if (ck < KDIM / 32 - 1) {
            STS_CHUNK();
            __syncthreads();
        }
    }

    // ---- epilogue: bias + store ----
    const int gr = lane >> 2;           // group row
    const int gc = (lane & 3) << 1;     // group col pair
#pragma unroll
    for (int nt = 0; nt < 8; nt++) {
        int col = n0 + wn * 64 + nt * 8 + gc;
        float2 bb = *(const float2*)(bias + col);
#pragma unroll
        for (int mt = 0; mt < 2; mt++) {
            int row = m0 + wm * 32 + mt * 16 + gr;
            float2 v0, v1;
            v0.x = acc[mt][nt][0] + bb.x;
            v0.y = acc[mt][nt][1] + bb.y;
            v1.x = acc[mt][nt][2] + bb.x;
            v1.y = acc[mt][nt][3] + bb.y;
            *(float2*)(C + (size_t)row * N + col)       = v0;
            *(float2*)(C + (size_t)(row + 8) * N + col) = v1;
        }
    }
#undef LDG_CHUNK
#undef STS_CHUNK
}

// ---------------------------------------------------------------------------
// RoPE in-place on q,k slices of g_qkv. One thread per pair.
// ---------------------------------------------------------------------------
__global__ void rope_kernel(float* __restrict__ qkv, const float* __restrict__ cache)
{
    int i = blockIdx.x * blockDim.x + threadIdx.x;
    const int total = BATCH * SEQ * 2 * HEADS * (HDIM / 2);
    if (i >= total) return;
    int d2   = i & 31;
    int h    = (i >> 5) & 15;
    int kind = (i >> 9) & 1;
    int s    = (i >> 10) & (SEQ - 1);
    int b    = i >> 21;

    size_t base = ((size_t)(b * SEQ + s)) * QKVW + kind * HID + h * HDIM + d2 * 2;
    float2 x  = *(float2*)(qkv + base);
    int pos = s & 255;
    float2 cs = *(const float2*)(cache + (pos * 32 + d2) * 2);
    float y0 = x.x * cs.x - x.y * cs.y;
    float y1 = x.y * cs.x + x.x * cs.y;
    *(float2*)(qkv + base) = make_float2(y0, y1);
}

// ---------------------------------------------------------------------------
// Banded attention (fp32), unchanged from the 1072us baseline.
// ---------------------------------------------------------------------------
#define QT   64
#define KTIL 5
#define QS   65
#define SCW  321

__global__ __launch_bounds__(256) void attn_kernel(
    const float* __restrict__ qkv, float* __restrict__ att)
{
    extern __shared__ float smf[];
    float* q_s  = smf;
    float* kv_s = smf + QT * QS;
    float* sc   = smf + 2 * QT * QS;
    float* red  = sc + QT * SCW;

    const int tid = threadIdx.x;
    const int q0 = blockIdx.x * QT;
    const int h  = blockIdx.y;
    const int b  = blockIdx.z;
    const int kb = q0 - 128;

    const float* qbase = qkv + ((size_t)(b * SEQ + q0)) * QKVW + h * HDIM;

#pragma unroll
    for (int i = 0; i < 4; i++) {
        int lin = tid + i * 256;
        int r  = lin >> 4;
        int c4 = (lin & 15) * 4;
        float4 v = *(const float4*)(qbase + (size_t)r * QKVW + c4);
        q_s[r * QS + c4 + 0] = v.x;
        q_s[r * QS + c4 + 1] = v.y;
        q_s[r * QS + c4 + 2] = v.z;
        q_s[r * QS + c4 + 3] = v.w;
    }

    const int tr = tid >> 4, tc = tid & 15;
    const int rm = tr * 4, cn = tc * 4;
    const float scale = 0.125f;

    for (int t = 0; t < KTIL; t++) {
        __syncthreads();
#pragma unroll
        for (int i = 0; i < 4; i++) {
            int lin = tid + i * 256;
            int r  = lin >> 4;
            int c4 = (lin & 15) * 4;
            int kj = kb + t * 64 + r;
            float4 v = make_float4(0.f, 0.f, 0.f, 0.f);
            if (kj >= 0 && kj < SEQ)
                v = *(const float4*)(qkv + ((size_t)(b * SEQ + kj)) * QKVW + HID + h * HDIM + c4);
            kv_s[r * QS + c4 + 0] = v.x;
            kv_s[r * QS + c4 + 1] = v.y;
            kv_s[r * QS + c4 + 2] = v.z;
            kv_s[r * QS + c4 + 3] = v.w;
        }
        __syncthreads();

        float acc[4][4];
#pragma unroll
        for (int i = 0; i < 4; i++)
#pragma unroll
            for (int j = 0; j < 4; j++) acc[i][j] = 0.0f;

#pragma unroll 8
        for (int d = 0; d < HDIM; d++) {
            float a[4], bb[4];
#pragma unroll
            for (int i = 0; i < 4; i++) a[i] = q_s[(rm + i) * QS + d];
#pragma unroll
            for (int j = 0; j < 4; j++) bb[j] = kv_s[(cn + j) * QS + d];
#pragma unroll
            for (int i = 0; i < 4; i++)
#pragma unroll
                for (int j = 0; j < 4; j++)
                    acc[i][j] += a[i] * bb[j];
        }

#pragma unroll
        for (int i = 0; i < 4; i++) {
            int qi = q0 + rm + i;
#pragma unroll
            for (int j = 0; j < 4; j++) {
                int kj = kb + t * 64 + cn + j;
                int rel = qi - kj;
                bool valid = (kj >= 0) && (kj < SEQ) && (rel <= 128) && (rel >= -128);
                sc[(rm + i) * SCW + t * 64 + cn + j] = valid ? acc[i][j] * scale : -1e30f;
            }
        }
    }
    __syncthreads();

    {
        const int part = tid >> 6;
        const int row  = tid & 63;
        const int c0 = part * 80;
        float mx = -1e30f;
        for (int c = c0; c < c0 + 80; c++) mx = fmaxf(mx, sc[row * SCW + c]);
        red[part * 64 + row] = mx;
        __syncthreads();
        float m = fmaxf(fmaxf(red[row], red[64 + row]),
                        fmaxf(red[128 + row], red[192 + row]));
        __syncthreads();
        float sumv = 0.0f;
        for (int c = c0; c < c0 + 80; c++) {
            float e = __expf(sc[row * SCW + c] - m);
            sc[row * SCW + c] = e;
            sumv += e;
        }
        red[part * 64 + row] = sumv;
    }
    __syncthreads();

    float acc2[4][4];
#pragma unroll
    for (int i = 0; i < 4; i++)
#pragma unroll
        for (int j = 0; j < 4; j++) acc2[i][j] = 0.0f;

    const int dn = tc * 4;
    for (int t = 0; t < KTIL; t++) {
        __syncthreads();
#pragma unroll
        for (int i = 0; i < 4; i++) {
            int lin = tid + i * 256;
            int r  = lin >> 4;
            int c4 = (lin & 15) * 4;
            int kj = kb + t * 64 + r;
            float4 v = make_float4(0.f, 0.f, 0.f, 0.f);
            if (kj >= 0 && kj < SEQ)
                v = *(const float4*)(qkv + ((size_t)(b * SEQ + kj)) * QKVW + 2 * HID + h * HDIM + c4);
            kv_s[r * QS + c4 + 0] = v.x;
            kv_s[r * QS + c4 + 1] = v.y;
            kv_s[r * QS + c4 + 2] = v.z;
            kv_s[r * QS + c4 + 3] = v.w;
        }
        __syncthreads();

#pragma unroll 8
        for (int c = 0; c < 64; c++) {
            float a[4], bb[4];
#pragma unroll
            for (int i = 0; i < 4; i++) a[i] = sc[(rm + i) * SCW + t * 64 + c];
#pragma unroll
            for (int j = 0; j < 4; j++) bb[j] = kv_s[c * QS + dn + j];
#pragma unroll
            for (int i = 0; i < 4; i++)
#pragma unroll
                for (int j = 0; j < 4; j++)
                    acc2[i][j] += a[i] * bb[j];
        }
    }

#pragma unroll
    for (int i = 0; i < 4; i++) {
        int r = rm + i;
        float rs = red[r] + red[64 + r] + red[128 + r] + red[192 + r];
        float inv = 1.0f / rs;
        int qi = q0 + r;
        float4 v;
        v.x = acc2[i][0] * inv;
        v.y = acc2[i][1] * inv;
        v.z = acc2[i][2] * inv;
        v.w = acc2[i][3] * inv;
        *(float4*)(att + ((size_t)((b * SEQ + qi) * HEADS + h)) * HDIM + dn) = v;
    }
}

// ---------------------------------------------------------------------------
// Launch
// ---------------------------------------------------------------------------
extern "C" void kernel_launch(void* const* d_in, const int* in_sizes, int n_in,
                              void* d_out, int out_size)
{
    const float* hs   = (const float*)d_in[0];
    const float* wqkv = (const float*)d_in[1];
    const float* bqkv = (const float*)d_in[2];
    const float* wo   = (const float*)d_in[3];
    const float* bo   = (const float*)d_in[4];
    const float* rope = (const float*)d_in[5];
    float* out = (float*)d_out;

    float *qkv, *att;
    cudaGetSymbolAddress((void**)&qkv, g_qkv);
    cudaGetSymbolAddress((void**)&att, g_att);

    // 1) QKV projection (tf32 tensor cores)
    gemm_tf32<<<dim3(QKVW / 128, MROWS / 128), 256>>>(hs, wqkv, bqkv, qkv, QKVW);

    // 2) RoPE on q,k
    {
        const int total = BATCH * SEQ * 2 * HEADS * (HDIM / 2);
        rope_kernel<<<(total + 255) / 256, 256>>>(qkv, rope);
    }

    // 3) Banded attention
    {
        const int asm_smem = (2 * QT * QS + QT * SCW + 4 * 64) * (int)sizeof(float);
        cudaFuncSetAttribute(attn_kernel,
                             cudaFuncAttributeMaxDynamicSharedMemorySize, asm_smem);
        attn_kernel<<<dim3(SEQ / QT, HEADS, BATCH), 256, asm_smem>>>(qkv, att);
    }

    // 4) Output projection (tf32 tensor cores)
    gemm_tf32<<<dim3(HID / 128, MROWS / 128), 256>>>(att, wo, bo, out, HID);
}

// round 8
// speedup vs baseline: 2.1090x; 1.0582x over previous
#include <cuda_runtime.h>
#include <cuda_bf16.h>
#include <cstdint>

// Problem constants
#define BATCH 2
#define SEQ   2048
#define HID   1024
#define HEADS 16
#define HDIM  64
#define QKVW  (3*HID)      // 3072
#define MROWS (BATCH*SEQ)  // 4096
#define KDIM  1024

// Scratch (device globals — no allocation allowed)
__device__ float g_qkv[(size_t)MROWS * QKVW];   // [B,S,3,H,D]
__device__ float g_att[(size_t)MROWS * HID];    // [B,S,H,D]

// ---------------------------------------------------------------------------
// tf32 helpers
// ---------------------------------------------------------------------------
__device__ __forceinline__ float tf32r(float x) {
    uint32_t u;
    asm("cvt.rna.tf32.f32 %0, %1;" : "=r"(u) : "f"(x));
    return __uint_as_float(u);
}

__device__ __forceinline__ void mma_tf32(float* d, const uint32_t* a, const uint32_t* b) {
    asm volatile(
        "mma.sync.aligned.m16n8k8.row.col.f32.tf32.tf32.f32 "
        "{%0,%1,%2,%3}, {%4,%5,%6,%7}, {%8,%9}, {%0,%1,%2,%3};\n"
        : "+f"(d[0]), "+f"(d[1]), "+f"(d[2]), "+f"(d[3])
        : "r"(a[0]), "r"(a[1]), "r"(a[2]), "r"(a[3]),
          "r"(b[0]), "r"(b[1]));
}

// ---------------------------------------------------------------------------
// tf32 mma GEMM:  C[M,N] = A[M,1024] @ B[1024,N] + bias[N]
// CTA tile 128x128, K-chunk 32, 256 threads (8 warps, 4x2 grid of 32x64).
// Fragment-permuted SMEM, DOUBLE-BUFFERED (STS overlaps mma).
// ---------------------------------------------------------------------------
__global__ __launch_bounds__(256) void gemm_tf32(
    const float* __restrict__ A, const float* __restrict__ B,
    const float* __restrict__ bias, float* __restrict__ C, int N)
{
    __shared__ float As[2][4096];   // 128 rows x 32 k, fragment-permuted
    __shared__ float Bs[2][4096];   // 32 k x 128 cols, fragment-permuted

    const int tid  = threadIdx.x;
    const int lane = tid & 31;
    const int wid  = tid >> 5;
    const int wm   = wid >> 1;          // 0..3  (rows)
    const int wn   = wid & 1;           // 0..1  (cols)
    const int m0 = blockIdx.y * 128, n0 = blockIdx.x * 128;

    float acc[2][8][4];
#pragma unroll
    for (int i = 0; i < 2; i++)
#pragma unroll
        for (int j = 0; j < 8; j++)
#pragma unroll
            for (int c = 0; c < 4; c++) acc[i][j][c] = 0.0f;

    float4 pa[4], pb[4];

#define LDG_CHUNK(k0)                                                          \
    {                                                                          \
        _Pragma("unroll")                                                      \
        for (int i = 0; i < 4; i++) {                                          \
            int idx = tid + i * 256;                                           \
            int row = idx >> 3, c4 = (idx & 7) << 2;                           \
            pa[i] = *(const float4*)(A + (size_t)(m0 + row) * KDIM + (k0) + c4);\
            int kk = idx >> 5, n4 = (idx & 31) << 2;                           \
            pb[i] = *(const float4*)(B + (size_t)((k0) + kk) * N + n0 + n4);   \
        }                                                                      \
    }

#define STS_CHUNK(st)                                                          \
    {                                                                          \
        _Pragma("unroll")                                                      \
        for (int i = 0; i < 4; i++) {                                          \
            int idx = tid + i * 256;                                           \
            {                                                                  \
                int row = idx >> 3, c4 = (idx & 7) << 2;                       \
                int tm = row >> 4, r = row & 15;                               \
                float v[4] = {pa[i].x, pa[i].y, pa[i].z, pa[i].w};             \
                _Pragma("unroll")                                              \
                for (int j = 0; j < 4; j++) {                                  \
                    int k  = c4 + j;                                           \
                    int tk = k >> 3;                                           \
                    int ln = ((r & 7) << 2) | (k & 3);                         \
                    int rg = (((k >> 2) & 1) << 1) | (r >> 3);                 \
                    As[st][(((tm << 2) | tk) << 7) + ((ln ^ tk) << 2) + rg] = tf32r(v[j]); \
                }                                                              \
            }                                                                  \
            {                                                                  \
                int kk = idx >> 5, n4 = (idx & 31) << 2;                       \
                int tk = kk >> 3;                                              \
                int rg = (kk >> 2) & 1;                                        \
                float v[4] = {pb[i].x, pb[i].y, pb[i].z, pb[i].w};             \
                _Pragma("unroll")                                              \
                for (int j = 0; j < 4; j++) {                                  \
                    int n  = n4 + j;                                           \
                    int tn = n >> 3;                                           \
                    int ln = ((n & 7) << 2) | (kk & 3);                        \
                    Bs[st][((tk * 16 + tn) << 6) + ((ln ^ (tn & 7)) << 1) + rg] = tf32r(v[j]); \
                }                                                              \
            }                                                                  \
        }                                                                      \
    }

    LDG_CHUNK(0);
    STS_CHUNK(0);
    __syncthreads();

    for (int ck = 0; ck < KDIM / 32; ck++) {
        const int cur = ck & 1;
        if (ck < KDIM / 32 - 1) LDG_CHUNK((ck + 1) * 32);

        // compute on current smem stage
#pragma unroll
        for (int kt = 0; kt < 4; kt++) {
            uint4 a[2];
            uint2 b[8];
#pragma unroll
            for (int mt = 0; mt < 2; mt++) {
                int tile = ((wm * 2 + mt) << 2) | kt;
                a[mt] = ((const uint4*)As[cur])[(tile << 5) + (lane ^ kt)];
            }
#pragma unroll
            for (int nt = 0; nt < 8; nt++) {
                int tn = wn * 8 + nt;
                b[nt] = ((const uint2*)Bs[cur])[((kt * 16 + tn) << 5) + (lane ^ (tn & 7))];
            }
#pragma unroll
            for (int mt = 0; mt < 2; mt++)
#pragma unroll
                for (int nt = 0; nt < 8; nt++)
                    mma_tf32(acc[mt][nt], (const uint32_t*)&a[mt], (const uint32_t*)&b[nt]);
        }
        if (ck < KDIM / 32 - 1) STS_CHUNK(cur ^ 1);
        __syncthreads();
    }

    // ---- epilogue: bias + store ----
    const int gr = lane >> 2;
    const int gc = (lane & 3) << 1;
#pragma unroll
    for (int nt = 0; nt < 8; nt++) {
        int col = n0 + wn * 64 + nt * 8 + gc;
        float2 bb = *(const float2*)(bias + col);
#pragma unroll
        for (int mt = 0; mt < 2; mt++) {
            int row = m0 + wm * 32 + mt * 16 + gr;
            float2 v0, v1;
            v0.x = acc[mt][nt][0] + bb.x;
            v0.y = acc[mt][nt][1] + bb.y;
            v1.x = acc[mt][nt][2] + bb.x;
            v1.y = acc[mt][nt][3] + bb.y;
            *(float2*)(C + (size_t)row * N + col)       = v0;
            *(float2*)(C + (size_t)(row + 8) * N + col) = v1;
        }
    }
#undef LDG_CHUNK
#undef STS_CHUNK
}

// ---------------------------------------------------------------------------
// RoPE in-place on q,k slices of g_qkv. One thread per pair.
// ---------------------------------------------------------------------------
__global__ void rope_kernel(float* __restrict__ qkv, const float* __restrict__ cache)
{
    int i = blockIdx.x * blockDim.x + threadIdx.x;
    const int total = BATCH * SEQ * 2 * HEADS * (HDIM / 2);
    if (i >= total) return;
    int d2   = i & 31;
    int h    = (i >> 5) & 15;
    int kind = (i >> 9) & 1;
    int s    = (i >> 10) & (SEQ - 1);
    int b    = i >> 21;

    size_t base = ((size_t)(b * SEQ + s)) * QKVW + kind * HID + h * HDIM + d2 * 2;
    float2 x  = *(float2*)(qkv + base);
    int pos = s & 255;
    float2 cs = *(const float2*)(cache + (pos * 32 + d2) * 2);
    float y0 = x.x * cs.x - x.y * cs.y;
    float y1 = x.y * cs.x + x.x * cs.y;
    *(float2*)(qkv + base) = make_float2(y0, y1);
}

// ---------------------------------------------------------------------------
// Banded attention with 3xTF32 mma for QK^T and PV.
// Block = (q-tile 64, head, batch), 256 threads (8 warps, 4x2 of 16x32).
// Exact softmax over the 320-key strip in SMEM.
// SMEM fragment layouts reuse the GEMM's verified permuted scheme:
//   A-layout (Q, 64x64):  slot = ((tm*8+tk)<<7) + ((ln^tk)<<2) + rg
//   B-layout (K/V, 64k x 64n): slot = ((kt*8+tn)<<6) + ((ln^(tn&7))<<1) + rg
// ---------------------------------------------------------------------------
#define QT   64
#define SCW  321
#define ATTN_SMEM ((4*4096 + 64*SCW + 256) * (int)sizeof(float))

__global__ __launch_bounds__(256) void attn_mma(
    const float* __restrict__ qkv, float* __restrict__ att)
{
    extern __shared__ float smf[];
    float* Qh = smf;              // 4096
    float* Ql = smf + 4096;       // 4096
    float* Kh = smf + 8192;       // 4096 (K or V, hi)
    float* Kl = smf + 12288;      // 4096 (K or V, lo)
    float* sc = smf + 16384;      // 64*SCW
    float* red = sc + 64 * SCW;   // 256

    const int tid  = threadIdx.x;
    const int lane = tid & 31, wid = tid >> 5;
    const int wm = wid >> 1, wn = wid & 1;
    const int q0 = blockIdx.x * QT;
    const int h  = blockIdx.y, b = blockIdx.z;
    const int kb = q0 - 128;
    const int gr = lane >> 2, gc = (lane & 3) << 1;

    // ---- load Q tile into A-layout (hi/lo split) ----
    {
        const float* qbase = qkv + ((size_t)(b * SEQ + q0)) * QKVW + h * HDIM;
#pragma unroll
        for (int i = 0; i < 4; i++) {
            int idx = tid + i * 256;
            int row = idx >> 4, c4 = (idx & 15) << 2;
            float4 v = *(const float4*)(qbase + (size_t)row * QKVW + c4);
            float vv[4] = {v.x, v.y, v.z, v.w};
#pragma unroll
            for (int j = 0; j < 4; j++) {
                int k = c4 + j;
                int tm = row >> 4, tk = k >> 3, r = row & 15;
                int ln = ((r & 7) << 2) | (k & 3);
                int rg = (((k >> 2) & 1) << 1) | (r >> 3);
                int slot = ((tm * 8 + tk) << 7) + ((ln ^ tk) << 2) + rg;
                float hi = tf32r(vv[j]);
                Qh[slot] = hi;
                Ql[slot] = tf32r(vv[j] - hi);
            }
        }
    }

    // ---- phase 1: scores into sc strip ----
    for (int t = 0; t < 5; t++) {
        __syncthreads();
        // K tile (64 keys x 64 d) into B-layout: k=d, n=key
#pragma unroll
        for (int i = 0; i < 4; i++) {
            int idx = tid + i * 256;
            int key = idx >> 4, c4 = (idx & 15) << 2;
            int kj = kb + t * 64 + key;
            float4 v = make_float4(0.f, 0.f, 0.f, 0.f);
            if (kj >= 0 && kj < SEQ)
                v = *(const float4*)(qkv + ((size_t)(b * SEQ + kj)) * QKVW + HID + h * HDIM + c4);
            float vv[4] = {v.x, v.y, v.z, v.w};
#pragma unroll
            for (int j = 0; j < 4; j++) {
                int d = c4 + j;
                int kt = d >> 3, tn = key >> 3;
                int ln = ((key & 7) << 2) | (d & 3);
                int rg = (d >> 2) & 1;
                int slot = ((kt * 8 + tn) << 6) + ((ln ^ (tn & 7)) << 1) + rg;
                float hi = tf32r(vv[j]);
                Kh[slot] = hi;
                Kl[slot] = tf32r(vv[j] - hi);
            }
        }
        __syncthreads();

        float c[4][4];
#pragma unroll
        for (int nt = 0; nt < 4; nt++)
#pragma unroll
            for (int e = 0; e < 4; e++) c[nt][e] = 0.0f;

#pragma unroll
        for (int kt = 0; kt < 8; kt++) {
            uint4 ah = ((const uint4*)Qh)[((wm * 8 + kt) << 5) + (lane ^ kt)];
            uint4 al = ((const uint4*)Ql)[((wm * 8 + kt) << 5) + (lane ^ kt)];
#pragma unroll
            for (int nt = 0; nt < 4; nt++) {
                int tn = wn * 4 + nt;
                uint2 bh = ((const uint2*)Kh)[((kt * 8 + tn) << 5) + (lane ^ (tn & 7))];
                uint2 bl = ((const uint2*)Kl)[((kt * 8 + tn) << 5) + (lane ^ (tn & 7))];
                mma_tf32(c[nt], (const uint32_t*)&ah, (const uint32_t*)&bh);
                mma_tf32(c[nt], (const uint32_t*)&ah, (const uint32_t*)&bl);
                mma_tf32(c[nt], (const uint32_t*)&al, (const uint32_t*)&bh);
            }
        }
        // masked write of C fragments to sc
#pragma unroll
        for (int nt = 0; nt < 4; nt++) {
#pragma unroll
            for (int half = 0; half < 2; half++) {
                int row = wm * 16 + gr + half * 8;
                int qi = q0 + row;
#pragma unroll
                for (int e = 0; e < 2; e++) {
                    int col = wn * 32 + nt * 8 + gc + e;
                    int kj = kb + t * 64 + col;
                    int rel = qi - kj;
                    bool valid = (kj >= 0) && (kj < SEQ) && (rel <= 128) && (rel >= -128);
                    sc[row * SCW + t * 64 + col] = valid ? c[nt][half * 2 + e] * 0.125f : -1e30f;
                }
            }
        }
    }
    __syncthreads();

    // ---- phase 2: exact softmax over 320 cols, 4 threads per row ----
    {
        const int part = tid >> 6;
        const int row  = tid & 63;
        const int c0 = part * 80;
        float mx = -1e30f;
        for (int c = c0; c < c0 + 80; c++) mx = fmaxf(mx, sc[row * SCW + c]);
        red[part * 64 + row] = mx;
        __syncthreads();
        float m = fmaxf(fmaxf(red[row], red[64 + row]),
                        fmaxf(red[128 + row], red[192 + row]));
        __syncthreads();
        float sumv = 0.0f;
        for (int c = c0; c < c0 + 80; c++) {
            float e = __expf(sc[row * SCW + c] - m);
            sc[row * SCW + c] = e;
            sumv += e;
        }
        red[part * 64 + row] = sumv;
    }

    // ---- phase 3: PV with 3xTF32 mma ----
    float o[4][4];
#pragma unroll
    for (int nt = 0; nt < 4; nt++)
#pragma unroll
        for (int e = 0; e < 4; e++) o[nt][e] = 0.0f;

    for (int t = 0; t < 5; t++) {
        __syncthreads();
        // V tile transposed into B-layout: k=key, n=dim
#pragma unroll
        for (int i = 0; i < 4; i++) {
            int idx = tid + i * 256;
            int key = idx >> 4, c4 = (idx & 15) << 2;
            int kj = kb + t * 64 + key;
            float4 v = make_float4(0.f, 0.f, 0.f, 0.f);
            if (kj >= 0 && kj < SEQ)
                v = *(const float4*)(qkv + ((size_t)(b * SEQ + kj)) * QKVW + 2 * HID + h * HDIM + c4);
            float vv[4] = {v.x, v.y, v.z, v.w};
#pragma unroll
            for (int j = 0; j < 4; j++) {
                int d = c4 + j;
                int kt = key >> 3, tn = d >> 3;
                int ln = ((d & 7) << 2) | (key & 3);
                int rg = (key >> 2) & 1;
                int slot = ((kt * 8 + tn) << 6) + ((ln ^ (tn & 7)) << 1) + rg;
                float hi = tf32r(vv[j]);
                Kh[slot] = hi;
                Kl[slot] = tf32r(vv[j] - hi);
            }
        }
        __syncthreads();

#pragma unroll
        for (int kt = 0; kt < 8; kt++) {
            int kk = t * 64 + kt * 8 + (lane & 3);
            int r0 = wm * 16 + gr;
            float p00 = sc[r0 * SCW + kk];
            float p10 = sc[(r0 + 8) * SCW + kk];
            float p01 = sc[r0 * SCW + kk + 4];
            float p11 = sc[(r0 + 8) * SCW + kk + 4];
            float ah[4], al[4];
            ah[0] = tf32r(p00); al[0] = tf32r(p00 - ah[0]);
            ah[1] = tf32r(p10); al[1] = tf32r(p10 - ah[1]);
            ah[2] = tf32r(p01); al[2] = tf32r(p01 - ah[2]);
            ah[3] = tf32r(p11); al[3] = tf32r(p11 - ah[3]);
#pragma unroll
            for (int nt = 0; nt < 4; nt++) {
                int tn = wn * 4 + nt;
                uint2 bh = ((const uint2*)Kh)[((kt * 8 + tn) << 5) + (lane ^ (tn & 7))];
                uint2 bl = ((const uint2*)Kl)[((kt * 8 + tn) << 5) + (lane ^ (tn & 7))];
                mma_tf32(o[nt], (const uint32_t*)ah, (const uint32_t*)&bh);
                mma_tf32(o[nt], (const uint32_t*)ah, (const uint32_t*)&bl);
                mma_tf32(o[nt], (const uint32_t*)al, (const uint32_t*)&bh);
            }
        }
    }

    // ---- epilogue: divide by row sums, store to att [B,S,H,D] ----
#pragma unroll
    for (int half = 0; half < 2; half++) {
        int row = wm * 16 + gr + half * 8;
        float rs = red[row] + red[64 + row] + red[128 + row] + red[192 + row];
        float inv = 1.0f / rs;
        int qi = q0 + row;
        float* obase = att + ((size_t)((b * SEQ + qi) * HEADS + h)) * HDIM;
#pragma unroll
        for (int nt = 0; nt < 4; nt++) {
            int col = wn * 32 + nt * 8 + gc;
            float2 v;
            v.x = o[nt][half * 2 + 0] * inv;
            v.y = o[nt][half * 2 + 1] * inv;
            *(float2*)(obase + col) = v;
        }
    }
}

// ---------------------------------------------------------------------------
// Launch
// ---------------------------------------------------------------------------
extern "C" void kernel_launch(void* const* d_in, const int* in_sizes, int n_in,
                              void* d_out, int out_size)
{
    const float* hs   = (const float*)d_in[0];
    const float* wqkv = (const float*)d_in[1];
    const float* bqkv = (const float*)d_in[2];
    const float* wo   = (const float*)d_in[3];
    const float* bo   = (const float*)d_in[4];
    const float* rope = (const float*)d_in[5];
    float* out = (float*)d_out;

    float *qkv, *att;
    cudaGetSymbolAddress((void**)&qkv, g_qkv);
    cudaGetSymbolAddress((void**)&att, g_att);

    // 1) QKV projection (tf32 tensor cores, double-buffered)
    gemm_tf32<<<dim3(QKVW / 128, MROWS / 128), 256>>>(hs, wqkv, bqkv, qkv, QKVW);

    // 2) RoPE on q,k
    {
        const int total = BATCH * SEQ * 2 * HEADS * (HDIM / 2);
        rope_kernel<<<(total + 255) / 256, 256>>>(qkv, rope);
    }

    // 3) Banded attention (3xTF32 mma)
    cudaFuncSetAttribute(attn_mma,
                         cudaFuncAttributeMaxDynamicSharedMemorySize, ATTN_SMEM);
    attn_mma<<<dim3(SEQ / QT, HEADS, BATCH), 256, ATTN_SMEM>>>(qkv, att);

    // 4) Output projection (tf32 tensor cores, double-buffered)
    gemm_tf32<<<dim3(HID / 128, MROWS / 128), 256>>>(att, wo, bo, out, HID);
}

// round 10
// speedup vs baseline: 2.5507x; 1.2094x over previous
#include <cuda_runtime.h>
#include <cuda_bf16.h>
#include <cstdint>

// Problem constants
#define BATCH 2
#define SEQ   2048
#define HID   1024
#define HEADS 16
#define HDIM  64
#define QKVW  (3*HID)      // 3072
#define MROWS (BATCH*SEQ)  // 4096
#define KDIM  1024

// Scratch (device globals — no allocation allowed)
__device__ float g_qkv[(size_t)MROWS * QKVW];   // [B,S,3,H,D]
__device__ float g_att[(size_t)MROWS * HID];    // [B,S,H,D] (tf32-rounded)
__device__ float g_hsr[(size_t)MROWS * KDIM];   // hs, tf32-rounded
__device__ float g_wqT[(size_t)QKVW * KDIM];    // Wqkv^T [N][K], tf32-rounded
__device__ float g_woT[(size_t)HID * KDIM];     // Wo^T   [N][K], tf32-rounded

// ---------------------------------------------------------------------------
// PTX helpers
// ---------------------------------------------------------------------------
__device__ __forceinline__ float tf32r(float x) {
    uint32_t u;
    asm("cvt.rna.tf32.f32 %0, %1;" : "=r"(u) : "f"(x));
    return __uint_as_float(u);
}
__device__ __forceinline__ uint32_t s2u(const void* p) {
    uint32_t a;
    asm("{ .reg .u64 t; cvta.to.shared.u64 t, %1; cvt.u32.u64 %0, t; }"
        : "=r"(a) : "l"(p));
    return a;
}
__device__ __forceinline__ void mma_tf32(float* d, const uint32_t* a, const uint32_t* b) {
    asm volatile(
        "mma.sync.aligned.m16n8k8.row.col.f32.tf32.tf32.f32 "
        "{%0,%1,%2,%3}, {%4,%5,%6,%7}, {%8,%9}, {%0,%1,%2,%3};\n"
        : "+f"(d[0]), "+f"(d[1]), "+f"(d[2]), "+f"(d[3])
        : "r"(a[0]), "r"(a[1]), "r"(a[2]), "r"(a[3]),
          "r"(b[0]), "r"(b[1]));
}
__device__ __forceinline__ void cp_async16(uint32_t saddr, const void* g) {
    asm volatile("cp.async.cg.shared.global [%0], [%1], 16;" :: "r"(saddr), "l"(g));
}
__device__ __forceinline__ void cp_commit() {
    asm volatile("cp.async.commit_group;" ::: "memory");
}
__device__ __forceinline__ void cp_wait1() {
    asm volatile("cp.async.wait_group 1;" ::: "memory");
}
__device__ __forceinline__ void ldsm_x4(uint32_t* r, uint32_t addr) {
    asm volatile("ldmatrix.sync.aligned.m8n8.x4.shared.b16 {%0,%1,%2,%3}, [%4];"
                 : "=r"(r[0]), "=r"(r[1]), "=r"(r[2]), "=r"(r[3]) : "r"(addr));
}

// ---------------------------------------------------------------------------
// Pre-pass kernels: tf32 rounding / transpose+round
// ---------------------------------------------------------------------------
__global__ void round_tf32(const float* __restrict__ x, float* __restrict__ y, int n)
{
    int i = (blockIdx.x * blockDim.x + threadIdx.x) * 4;
    if (i >= n) return;
    float4 v = *(const float4*)(x + i);
    v.x = tf32r(v.x); v.y = tf32r(v.y); v.z = tf32r(v.z); v.w = tf32r(v.w);
    *(float4*)(y + i) = v;
}

__global__ void transpose_round(const float* __restrict__ W, float* __restrict__ T,
                                int K, int N)
{
    __shared__ float t[32][33];
    int n0 = blockIdx.x * 32, k0 = blockIdx.y * 32;
    int tx = threadIdx.x, ty = threadIdx.y;
#pragma unroll
    for (int i = 0; i < 4; i++)
        t[ty + 8 * i][tx] = W[(size_t)(k0 + ty + 8 * i) * N + n0 + tx];
    __syncthreads();
#pragma unroll
    for (int i = 0; i < 4; i++)
        T[(size_t)(n0 + ty + 8 * i) * K + k0 + tx] = tf32r(t[tx][ty + 8 * i]);
}

// ---------------------------------------------------------------------------
// tf32 GEMM, cp.async + ldmatrix + mma:
//   C[M,N] = A[M,1024] @ Bt[N,1024]^T + bias[N]
// A, Bt are K-major, PRE-ROUNDED to tf32. CTA tile 128x128, K-chunk 32,
// 256 threads (8 warps, 4m x 2n of 32x64). 3-stage cp.async pipeline.
// SMEM per stage: A 16KB + B 16KB, layout [row][k] with chunk swizzle c^=row&7.
// ---------------------------------------------------------------------------
#define GSMEM (3 * 32768)

__global__ __launch_bounds__(256) void gemm_tf32_cp(
    const float* __restrict__ A, const float* __restrict__ Bt,
    const float* __restrict__ bias, float* __restrict__ C, int N)
{
    extern __shared__ char smc[];
    const uint32_t sbase = s2u(smc);
    const int tid = threadIdx.x, lane = tid & 31, wid = tid >> 5;
    const int wm = wid >> 1, wn = wid & 1;
    const int m0 = blockIdx.y * 128, n0 = blockIdx.x * 128;

    float acc[2][8][4];
#pragma unroll
    for (int i = 0; i < 2; i++)
#pragma unroll
        for (int j = 0; j < 8; j++)
#pragma unroll
            for (int c = 0; c < 4; c++) acc[i][j][c] = 0.0f;

#define ISSUE(ck, st)                                                         \
    {                                                                         \
        const float* pA_ = A + (size_t)m0 * KDIM + (ck) * 32;                 \
        const float* pB_ = Bt + (size_t)n0 * KDIM + (ck) * 32;                \
        uint32_t sa_ = sbase + (uint32_t)(st) * 32768u;                       \
        _Pragma("unroll")                                                     \
        for (int i_ = 0; i_ < 4; i_++) {                                      \
            int u_ = tid + i_ * 256;                                          \
            int row_ = u_ >> 3, c_ = u_ & 7;                                  \
            uint32_t off_ = row_ * 128 + ((c_ ^ (row_ & 7)) << 4);            \
            cp_async16(sa_ + off_, pA_ + (size_t)row_ * KDIM + c_ * 4);       \
            cp_async16(sa_ + 16384u + off_, pB_ + (size_t)row_ * KDIM + c_ * 4); \
        }                                                                     \
    }

    ISSUE(0, 0); cp_commit();
    ISSUE(1, 1); cp_commit();

    const int g = lane >> 3, l7 = lane & 7;
    int st = 0;
    for (int ck = 0; ck < KDIM / 32; ck++) {
        cp_wait1();
        __syncthreads();                 // all warps done with stage (ck-1)%3
        int nst = st + 2; if (nst >= 3) nst -= 3;
        if (ck + 2 < KDIM / 32) ISSUE(ck + 2, nst);
        cp_commit();

        uint32_t sa = sbase + (uint32_t)st * 32768u;
        uint32_t sb = sa + 16384u;
#pragma unroll
        for (int kt = 0; kt < 4; kt++) {
            uint32_t a[2][4];
#pragma unroll
            for (int mt = 0; mt < 2; mt++) {
                int row = wm * 32 + mt * 16 + ((g & 1) << 3) + l7;
                int c = 2 * kt + (g >> 1);
                ldsm_x4(a[mt], sa + row * 128 + ((c ^ l7) << 4));
            }
            uint32_t b[8][2];
#pragma unroll
            for (int p = 0; p < 4; p++) {
                int row = wn * 64 + p * 16 + ((g >> 1) << 3) + l7;
                int c = 2 * kt + (g & 1);
                uint32_t r4[4];
                ldsm_x4(r4, sb + row * 128 + ((c ^ l7) << 4));
                b[2 * p][0] = r4[0]; b[2 * p][1] = r4[1];
                b[2 * p + 1][0] = r4[2]; b[2 * p + 1][1] = r4[3];
            }
#pragma unroll
            for (int mt = 0; mt < 2; mt++)
#pragma unroll
                for (int nt = 0; nt < 8; nt++)
                    mma_tf32(acc[mt][nt], a[mt], b[nt]);
        }
        st++; if (st == 3) st = 0;
    }
#undef ISSUE

    // ---- epilogue: bias + store ----
    const int gr = lane >> 2;
    const int gc = (lane & 3) << 1;
#pragma unroll
    for (int nt = 0; nt < 8; nt++) {
        int col = n0 + wn * 64 + nt * 8 + gc;
        float2 bb = *(const float2*)(bias + col);
#pragma unroll
        for (int mt = 0; mt < 2; mt++) {
            int row = m0 + wm * 32 + mt * 16 + gr;
            float2 v0, v1;
            v0.x = acc[mt][nt][0] + bb.x;
            v0.y = acc[mt][nt][1] + bb.y;
            v1.x = acc[mt][nt][2] + bb.x;
            v1.y = acc[mt][nt][3] + bb.y;
            *(float2*)(C + (size_t)row * N + col)       = v0;
            *(float2*)(C + (size_t)(row + 8) * N + col) = v1;
        }
    }
}

// ---------------------------------------------------------------------------
// RoPE in-place on q,k slices of g_qkv. One thread per pair.
// ---------------------------------------------------------------------------
__global__ void rope_kernel(float* __restrict__ qkv, const float* __restrict__ cache)
{
    int i = blockIdx.x * blockDim.x + threadIdx.x;
    const int total = BATCH * SEQ * 2 * HEADS * (HDIM / 2);
    if (i >= total) return;
    int d2   = i & 31;
    int h    = (i >> 5) & 15;
    int kind = (i >> 9) & 1;
    int s    = (i >> 10) & (SEQ - 1);
    int b    = i >> 21;

    size_t base = ((size_t)(b * SEQ + s)) * QKVW + kind * HID + h * HDIM + d2 * 2;
    float2 x  = *(float2*)(qkv + base);
    int pos = s & 255;
    float2 cs = *(const float2*)(cache + (pos * 32 + d2) * 2);
    float y0 = x.x * cs.x - x.y * cs.y;
    float y1 = x.y * cs.x + x.x * cs.y;
    *(float2*)(qkv + base) = make_float2(y0, y1);
}

// ---------------------------------------------------------------------------
// Banded attention with 3xTF32 mma for QK^T and PV (unchanged from round 6,
// except the epilogue stores tf32-rounded values so the Wo GEMM can consume
// g_att directly).
// ---------------------------------------------------------------------------
#define QT   64
#define SCW  321
#define ATTN_SMEM ((4*4096 + 64*SCW + 256) * (int)sizeof(float))

__global__ __launch_bounds__(256) void attn_mma(
    const float* __restrict__ qkv, float* __restrict__ att)
{
    extern __shared__ float smf[];
    float* Qh = smf;
    float* Ql = smf + 4096;
    float* Kh = smf + 8192;
    float* Kl = smf + 12288;
    float* sc = smf + 16384;
    float* red = sc + 64 * SCW;

    const int tid  = threadIdx.x;
    const int lane = tid & 31, wid = tid >> 5;
    const int wm = wid >> 1, wn = wid & 1;
    const int q0 = blockIdx.x * QT;
    const int h  = blockIdx.y, b = blockIdx.z;
    const int kb = q0 - 128;
    const int gr = lane >> 2, gc = (lane & 3) << 1;

    {
        const float* qbase = qkv + ((size_t)(b * SEQ + q0)) * QKVW + h * HDIM;
#pragma unroll
        for (int i = 0; i < 4; i++) {
            int idx = tid + i * 256;
            int row = idx >> 4, c4 = (idx & 15) << 2;
            float4 v = *(const float4*)(qbase + (size_t)row * QKVW + c4);
            float vv[4] = {v.x, v.y, v.z, v.w};
#pragma unroll
            for (int j = 0; j < 4; j++) {
                int k = c4 + j;
                int tm = row >> 4, tk = k >> 3, r = row & 15;
                int ln = ((r & 7) << 2) | (k & 3);
                int rg = (((k >> 2) & 1) << 1) | (r >> 3);
                int slot = ((tm * 8 + tk) << 7) + ((ln ^ tk) << 2) + rg;
                float hi = tf32r(vv[j]);
                Qh[slot] = hi;
                Ql[slot] = tf32r(vv[j] - hi);
            }
        }
    }

    for (int t = 0; t < 5; t++) {
        __syncthreads();
#pragma unroll
        for (int i = 0; i < 4; i++) {
            int idx = tid + i * 256;
            int key = idx >> 4, c4 = (idx & 15) << 2;
            int kj = kb + t * 64 + key;
            float4 v = make_float4(0.f, 0.f, 0.f, 0.f);
            if (kj >= 0 && kj < SEQ)
                v = *(const float4*)(qkv + ((size_t)(b * SEQ + kj)) * QKVW + HID + h * HDIM + c4);
            float vv[4] = {v.x, v.y, v.z, v.w};
#pragma unroll
            for (int j = 0; j < 4; j++) {
                int d = c4 + j;
                int kt = d >> 3, tn = key >> 3;
                int ln = ((key & 7) << 2) | (d & 3);
                int rg = (d >> 2) & 1;
                int slot = ((kt * 8 + tn) << 6) + ((ln ^ (tn & 7)) << 1) + rg;
                float hi = tf32r(vv[j]);
                Kh[slot] = hi;
                Kl[slot] = tf32r(vv[j] - hi);
            }
        }
        __syncthreads();

        float c[4][4];
#pragma unroll
        for (int nt = 0; nt < 4; nt++)
#pragma unroll
            for (int e = 0; e < 4; e++) c[nt][e] = 0.0f;

#pragma unroll
        for (int kt = 0; kt < 8; kt++) {
            uint4 ah = ((const uint4*)Qh)[((wm * 8 + kt) << 5) + (lane ^ kt)];
            uint4 al = ((const uint4*)Ql)[((wm * 8 + kt) << 5) + (lane ^ kt)];
#pragma unroll
            for (int nt = 0; nt < 4; nt++) {
                int tn = wn * 4 + nt;
                uint2 bh = ((const uint2*)Kh)[((kt * 8 + tn) << 5) + (lane ^ (tn & 7))];
                uint2 bl = ((const uint2*)Kl)[((kt * 8 + tn) << 5) + (lane ^ (tn & 7))];
                mma_tf32(c[nt], (const uint32_t*)&ah, (const uint32_t*)&bh);
                mma_tf32(c[nt], (const uint32_t*)&ah, (const uint32_t*)&bl);
                mma_tf32(c[nt], (const uint32_t*)&al, (const uint32_t*)&bh);
            }
        }
#pragma unroll
        for (int nt = 0; nt < 4; nt++) {
#pragma unroll
            for (int half = 0; half < 2; half++) {
                int row = wm * 16 + gr + half * 8;
                int qi = q0 + row;
#pragma unroll
                for (int e = 0; e < 2; e++) {
                    int col = wn * 32 + nt * 8 + gc + e;
                    int kj = kb + t * 64 + col;
                    int rel = qi - kj;
                    bool valid = (kj >= 0) && (kj < SEQ) && (rel <= 128) && (rel >= -128);
                    sc[row * SCW + t * 64 + col] = valid ? c[nt][half * 2 + e] * 0.125f : -1e30f;
                }
            }
        }
    }
    __syncthreads();

    {
        const int part = tid >> 6;
        const int row  = tid & 63;
        const int c0 = part * 80;
        float mx = -1e30f;
        for (int c = c0; c < c0 + 80; c++) mx = fmaxf(mx, sc[row * SCW + c]);
        red[part * 64 + row] = mx;
        __syncthreads();
        float m = fmaxf(fmaxf(red[row], red[64 + row]),
                        fmaxf(red[128 + row], red[192 + row]));
        __syncthreads();
        float sumv = 0.0f;
        for (int c = c0; c < c0 + 80; c++) {
            float e = __expf(sc[row * SCW + c] - m);
            sc[row * SCW + c] = e;
            sumv += e;
        }
        red[part * 64 + row] = sumv;
    }

    float o[4][4];
#pragma unroll
    for (int nt = 0; nt < 4; nt++)
#pragma unroll
        for (int e = 0; e < 4; e++) o[nt][e] = 0.0f;

    for (int t = 0; t < 5; t++) {
        __syncthreads();
#pragma unroll
        for (int i = 0; i < 4; i++) {
            int idx = tid + i * 256;
            int key = idx >> 4, c4 = (idx & 15) << 2;
            int kj = kb + t * 64 + key;
            float4 v = make_float4(0.f, 0.f, 0.f, 0.f);
            if (kj >= 0 && kj < SEQ)
                v = *(const float4*)(qkv + ((size_t)(b * SEQ + kj)) * QKVW + 2 * HID + h * HDIM + c4);
            float vv[4] = {v.x, v.y, v.z, v.w};
#pragma unroll
            for (int j = 0; j < 4; j++) {
                int d = c4 + j;
                int kt = key >> 3, tn = d >> 3;
                int ln = ((d & 7) << 2) | (key & 3);
                int rg = (key >> 2) & 1;
                int slot = ((kt * 8 + tn) << 6) + ((ln ^ (tn & 7)) << 1) + rg;
                float hi = tf32r(vv[j]);
                Kh[slot] = hi;
                Kl[slot] = tf32r(vv[j] - hi);
            }
        }
        __syncthreads();

#pragma unroll
        for (int kt = 0; kt < 8; kt++) {
            int kk = t * 64 + kt * 8 + (lane & 3);
            int r0 = wm * 16 + gr;
            float p00 = sc[r0 * SCW + kk];
            float p10 = sc[(r0 + 8) * SCW + kk];
            float p01 = sc[r0 * SCW + kk + 4];
            float p11 = sc[(r0 + 8) * SCW + kk + 4];
            float ah[4], al[4];
            ah[0] = tf32r(p00); al[0] = tf32r(p00 - ah[0]);
            ah[1] = tf32r(p10); al[1] = tf32r(p10 - ah[1]);
            ah[2] = tf32r(p01); al[2] = tf32r(p01 - ah[2]);
            ah[3] = tf32r(p11); al[3] = tf32r(p11 - ah[3]);
#pragma unroll
            for (int nt = 0; nt < 4; nt++) {
                int tn = wn * 4 + nt;
                uint2 bh = ((const uint2*)Kh)[((kt * 8 + tn) << 5) + (lane ^ (tn & 7))];
                uint2 bl = ((const uint2*)Kl)[((kt * 8 + tn) << 5) + (lane ^ (tn & 7))];
                mma_tf32(o[nt], (const uint32_t*)ah, (const uint32_t*)&bh);
                mma_tf32(o[nt], (const uint32_t*)ah, (const uint32_t*)&bl);
                mma_tf32(o[nt], (const uint32_t*)al, (const uint32_t*)&bh);
            }
        }
    }

    // epilogue: divide by row sums, store TF32-ROUNDED to att [B,S,H,D]
#pragma unroll
    for (int half = 0; half < 2; half++) {
        int row = wm * 16 + gr + half * 8;
        float rs = red[row] + red[64 + row] + red[128 + row] + red[192 + row];
        float inv = 1.0f / rs;
        int qi = q0 + row;
        float* obase = att + ((size_t)((b * SEQ + qi) * HEADS + h)) * HDIM;
#pragma unroll
        for (int nt = 0; nt < 4; nt++) {
            int col = wn * 32 + nt * 8 + gc;
            float2 v;
            v.x = tf32r(o[nt][half * 2 + 0] * inv);
            v.y = tf32r(o[nt][half * 2 + 1] * inv);
            *(float2*)(obase + col) = v;
        }
    }
}

// ---------------------------------------------------------------------------
// Launch
// ---------------------------------------------------------------------------
extern "C" void kernel_launch(void* const* d_in, const int* in_sizes, int n_in,
                              void* d_out, int out_size)
{
    const float* hs   = (const float*)d_in[0];
    const float* wqkv = (const float*)d_in[1];
    const float* bqkv = (const float*)d_in[2];
    const float* wo   = (const float*)d_in[3];
    const float* bo   = (const float*)d_in[4];
    const float* rope = (const float*)d_in[5];
    float* out = (float*)d_out;

    float *qkv, *att, *hsr, *wqT, *woT;
    cudaGetSymbolAddress((void**)&qkv, g_qkv);
    cudaGetSymbolAddress((void**)&att, g_att);
    cudaGetSymbolAddress((void**)&hsr, g_hsr);
    cudaGetSymbolAddress((void**)&wqT, g_wqT);
    cudaGetSymbolAddress((void**)&woT, g_woT);

    cudaFuncSetAttribute(gemm_tf32_cp,
                         cudaFuncAttributeMaxDynamicSharedMemorySize, GSMEM);
    cudaFuncSetAttribute(attn_mma,
                         cudaFuncAttributeMaxDynamicSharedMemorySize, ATTN_SMEM);

    // 0) Pre-pass: tf32-round hs; transpose+round weights to [N][K]
    round_tf32<<<(MROWS * KDIM) / 1024, 256>>>(hs, hsr, MROWS * KDIM);
    transpose_round<<<dim3(QKVW / 32, KDIM / 32), dim3(32, 8)>>>(wqkv, wqT, KDIM, QKVW);
    transpose_round<<<dim3(HID / 32, KDIM / 32), dim3(32, 8)>>>(wo, woT, KDIM, HID);

    // 1) QKV projection (cp.async + ldmatrix + tf32 mma)
    gemm_tf32_cp<<<dim3(QKVW / 128, MROWS / 128), 256, GSMEM>>>(hsr, wqT, bqkv, qkv, QKVW);

    // 2) RoPE on q,k
    {
        const int total = BATCH * SEQ * 2 * HEADS * (HDIM / 2);
        rope_kernel<<<(total + 255) / 256, 256>>>(qkv, rope);
    }

    // 3) Banded attention (3xTF32 mma), epilogue pre-rounds att for Wo GEMM
    attn_mma<<<dim3(SEQ / QT, HEADS, BATCH), 256, ATTN_SMEM>>>(qkv, att);

    // 4) Output projection
    gemm_tf32_cp<<<dim3(HID / 128, MROWS / 128), 256, GSMEM>>>(att, woT, bo, out, HID);
}